// round 1
// baseline (speedup 1.0000x reference)
#include <cuda_runtime.h>
#include <cstdint>

// Problem dims (fixed by the dataset)
#define NROWS   131072
#define D_IN    512
#define DH      128
#define NCODE   256
#define BETA    0.25

// padded row strides (floats) for conflict-free SMEM
#define CBP   132      // 33 float4
#define RP    132

// ---------------- scratch (no allocations allowed) ----------------
__device__ float  g_latent[(size_t)NROWS * DH];    // latent / remainder source
__device__ float  g_restored[(size_t)NROWS * DH];  // sum of chosen code vectors
__device__ double g_rq;
__device__ double g_recon;
__device__ int    g_used[3 * NCODE];

// ---------------- init ----------------
__global__ void k_init() {
    int t = threadIdx.x;
    if (t == 0) { g_rq = 0.0; g_recon = 0.0; }
    if (t < 3 * NCODE) g_used[t] = 0;
}

// ---------------- kernel 1: latent = emb @ W_enc^T ----------------
// grid 4096 CTAs x 128 thr; CTA computes 32 rows x 128 cols.
// thread tile: 8 rows x 4 cols; cols c = lane + 32*j.
__global__ __launch_bounds__(128) void k_latent(const float* __restrict__ emb,
                                                const float* __restrict__ Wenc) {
    __shared__ float sB[128 * 68];      // 128 cols x 64 k (pad to 68) = 34816B
    int t = threadIdx.x;
    int lane = t & 31, warp = t >> 5;   // warp = rowGroup (4 groups x 8 rows)
    int row0 = blockIdx.x * 32;

    float acc[8][4];
#pragma unroll
    for (int r = 0; r < 8; r++)
#pragma unroll
        for (int j = 0; j < 4; j++) acc[r][j] = 0.f;

    const float4* embv = (const float4*)emb;       // row stride 128 float4
    float4* sBv = (float4*)sB;                     // row stride 17 float4

    for (int kc = 0; kc < D_IN; kc += 64) {
        __syncthreads();
        // load W_enc[:, kc:kc+64] : 128 rows x 16 float4
#pragma unroll
        for (int i = 0; i < 16; i++) {
            int idx = t + i * 128;
            int c = idx >> 4, q = idx & 15;
            sBv[c * 17 + q] = *(const float4*)(Wenc + (size_t)c * D_IN + kc + q * 4);
        }
        __syncthreads();
#pragma unroll 2
        for (int q = 0; q < 16; q++) {
            float4 bv[4];
#pragma unroll
            for (int j = 0; j < 4; j++) bv[j] = sBv[(lane + 32 * j) * 17 + q];
#pragma unroll
            for (int r = 0; r < 8; r++) {
                float4 av = embv[(size_t)(row0 + warp * 8 + r) * 128 + (kc >> 2) + q];
#pragma unroll
                for (int j = 0; j < 4; j++) {
                    acc[r][j] += av.x * bv[j].x + av.y * bv[j].y
                               + av.z * bv[j].z + av.w * bv[j].w;
                }
            }
        }
    }
#pragma unroll
    for (int r = 0; r < 8; r++)
#pragma unroll
        for (int j = 0; j < 4; j++)
            g_latent[(size_t)(row0 + warp * 8 + r) * DH + lane + 32 * j] = acc[r][j];
}

// ---------------- kernel 2: residual quantization (3 levels fused) ----------------
// grid 4096 CTAs x 128 thr; CTA handles 32 rows. Codebook in SMEM per level.
// thread tile for scores: 8 rows x 8 codes; codes c = lane + 32*j (conflict-free).
#define RQ_SMEM ((NCODE * CBP + 32 * RP) * 4)
__global__ __launch_bounds__(128) void k_rq(const float* __restrict__ cb0,
                                            const float* __restrict__ cb1,
                                            const float* __restrict__ cb2) {
    extern __shared__ float sm[];
    float* cb_s  = sm;                  // 256 x 132
    float* rem_s = sm + NCODE * CBP;    // 32  x 132
    int t = threadIdx.x, lane = t & 31, warp = t >> 5;
    int row0 = blockIdx.x * 32;

    // load latent tile -> rem_s (1024 float4)
    const float4* lat = (const float4*)g_latent;
    float4* remv = (float4*)rem_s;                 // row stride 33 float4
#pragma unroll
    for (int i = 0; i < 8; i++) {
        int idx = t + i * 128;
        int r = idx >> 5, q = idx & 31;
        remv[r * 33 + q] = lat[(size_t)(row0 + r) * 32 + q];
    }

    float rst[8][4];
#pragma unroll
    for (int r = 0; r < 8; r++)
#pragma unroll
        for (int m = 0; m < 4; m++) rst[r][m] = 0.f;
    float rql = 0.f;

    const float* cbs[3] = {cb0, cb1, cb2};
    for (int L = 0; L < 3; L++) {
        __syncthreads();            // protect cb_s from previous level's readers
        const float4* src = (const float4*)cbs[L];
        float4* cbv = (float4*)cb_s;                // row stride 33 float4
#pragma unroll
        for (int i = 0; i < 64; i++) {              // 8192 float4
            int idx = t + i * 128;
            int c = idx >> 5, q = idx & 31;
            cbv[c * 33 + q] = src[c * 32 + q];
        }
        __syncthreads();

        float acc[8][8];
        float cn[8];
#pragma unroll
        for (int j = 0; j < 8; j++) cn[j] = 0.f;
#pragma unroll
        for (int r = 0; r < 8; r++)
#pragma unroll
            for (int j = 0; j < 8; j++) acc[r][j] = 0.f;

#pragma unroll 2
        for (int q = 0; q < 32; q++) {
            float4 bv[8];
#pragma unroll
            for (int j = 0; j < 8; j++) bv[j] = cbv[(lane + 32 * j) * 33 + q];
#pragma unroll
            for (int j = 0; j < 8; j++)
                cn[j] += bv[j].x * bv[j].x + bv[j].y * bv[j].y
                       + bv[j].z * bv[j].z + bv[j].w * bv[j].w;
#pragma unroll
            for (int r = 0; r < 8; r++) {
                float4 av = remv[(warp * 8 + r) * 33 + q];
#pragma unroll
                for (int j = 0; j < 8; j++) {
                    acc[r][j] += av.x * bv[j].x + av.y * bv[j].y
                               + av.z * bv[j].z + av.w * bv[j].w;
                }
            }
        }

        // per-row argmin of (||c||^2 - 2 r.c), lowest-index tie-break
#pragma unroll
        for (int r = 0; r < 8; r++) {
            float best = cn[0] - 2.f * acc[r][0];
            int bidx = lane;
#pragma unroll
            for (int j = 1; j < 8; j++) {
                float v = cn[j] - 2.f * acc[r][j];
                int ci = lane + 32 * j;
                if (v < best) { best = v; bidx = ci; }
            }
#pragma unroll
            for (int off = 16; off > 0; off >>= 1) {
                float ov = __shfl_xor_sync(0xffffffffu, best, off);
                int   oi = __shfl_xor_sync(0xffffffffu, bidx, off);
                if (ov < best || (ov == best && oi < bidx)) { best = ov; bidx = oi; }
            }
            int row = warp * 8 + r;
            if (lane == 0) g_used[L * NCODE + bidx] = 1;
#pragma unroll
            for (int m = 0; m < 4; m++) {
                int d = lane + 32 * m;
                float cv = cb_s[bidx * CBP + d];
                float nv = rem_s[row * RP + d] - cv;
                rem_s[row * RP + d] = nv;
                rql += nv * nv;          // (r - v)^2 == new remainder^2
                rst[r][m] += cv;
            }
        }
        __syncwarp();   // remainder rows are warp-private; warp-level fence suffices
    }

    // write restored (registers -> global, coalesced)
#pragma unroll
    for (int r = 0; r < 8; r++)
#pragma unroll
        for (int m = 0; m < 4; m++)
            g_restored[(size_t)(row0 + warp * 8 + r) * DH + lane + 32 * m] = rst[r][m];

    // reduce squared-remainder sum
#pragma unroll
    for (int off = 16; off > 0; off >>= 1)
        rql += __shfl_xor_sync(0xffffffffu, rql, off);
    if (lane == 0) atomicAdd(&g_rq, (double)rql);
}

// ---------------- kernel 3: recon = restored @ W_dec^T, fused MSE ----------------
// grid 4096 x 128 thr; 32 rows per CTA, D_IN in 4 chunks of 128 cols.
#define RECON_SMEM ((32 * RP + 128 * CBP) * 4)
__global__ __launch_bounds__(128) void k_recon(const float* __restrict__ emb,
                                               const float* __restrict__ Wdec) {
    extern __shared__ float sm[];
    float* sR = sm;             // 32 x 132
    float* sW = sm + 32 * RP;   // 128 x 132
    int t = threadIdx.x, lane = t & 31, warp = t >> 5;
    int row0 = blockIdx.x * 32;

    const float4* rsv = (const float4*)g_restored;
    float4* sRv = (float4*)sR;
#pragma unroll
    for (int i = 0; i < 8; i++) {
        int idx = t + i * 128;
        int r = idx >> 5, q = idx & 31;
        sRv[r * 33 + q] = rsv[(size_t)(row0 + r) * 32 + q];
    }

    float local = 0.f;
    for (int i0 = 0; i0 < D_IN; i0 += 128) {
        __syncthreads();
        const float4* src = (const float4*)(Wdec + (size_t)i0 * DH);
        float4* sWv = (float4*)sW;
#pragma unroll
        for (int i = 0; i < 32; i++) {              // 4096 float4
            int idx = t + i * 128;
            int c = idx >> 5, q = idx & 31;
            sWv[c * 33 + q] = src[c * 32 + q];
        }
        __syncthreads();

        float acc[8][4];
#pragma unroll
        for (int r = 0; r < 8; r++)
#pragma unroll
            for (int j = 0; j < 4; j++) acc[r][j] = 0.f;

#pragma unroll 2
        for (int q = 0; q < 32; q++) {
            float4 bv[4];
#pragma unroll
            for (int j = 0; j < 4; j++) bv[j] = sWv[(lane + 32 * j) * 33 + q];
#pragma unroll
            for (int r = 0; r < 8; r++) {
                float4 av = sRv[(warp * 8 + r) * 33 + q];
#pragma unroll
                for (int j = 0; j < 4; j++) {
                    acc[r][j] += av.x * bv[j].x + av.y * bv[j].y
                               + av.z * bv[j].z + av.w * bv[j].w;
                }
            }
        }
#pragma unroll
        for (int r = 0; r < 8; r++) {
            int row = row0 + warp * 8 + r;
#pragma unroll
            for (int j = 0; j < 4; j++) {
                int c = i0 + lane + 32 * j;
                float d = acc[r][j] - emb[(size_t)row * D_IN + c];
                local += d * d;
            }
        }
    }
#pragma unroll
    for (int off = 16; off > 0; off >>= 1)
        local += __shfl_xor_sync(0xffffffffu, local, off);
    if (lane == 0) atomicAdd(&g_recon, (double)local);
}

// ---------------- kernel 4: finalize ----------------
__global__ void k_finalize(float* __restrict__ out, int out_size) {
    __shared__ int cnt[3];
    int t = threadIdx.x;
    if (t < 3) cnt[t] = 0;
    __syncthreads();
    if (t < 3 * NCODE) { if (g_used[t]) atomicAdd(&cnt[t / NCODE], 1); }
    __syncthreads();
    if (t == 0) {
        double recon = g_recon / ((double)NROWS * (double)D_IN);
        double rq    = (1.0 + BETA) * g_rq / ((double)NROWS * (double)DH);
        float rf = (float)recon, qf = (float)rq;
        if (out_size > 0) out[0] = rf + qf;
        if (out_size > 1) out[1] = rf;
        if (out_size > 2) out[2] = qf;
        if (out_size > 3) out[3] = (float)cnt[0];
        if (out_size > 4) out[4] = (float)cnt[1];
        if (out_size > 5) out[5] = (float)cnt[2];
    }
    for (int i = 6 + t; i < out_size; i += blockDim.x) out[i] = 0.f;
}

// ---------------- launch ----------------
extern "C" void kernel_launch(void* const* d_in, const int* in_sizes, int n_in,
                              void* d_out, int out_size) {
    const float* emb  = (const float*)d_in[0];
    const float* Wenc = (const float*)d_in[1];
    const float* Wdec = (const float*)d_in[2];
    const float* cb0  = (const float*)d_in[3];
    const float* cb1  = (const float*)d_in[4];
    const float* cb2  = (const float*)d_in[5];

    cudaFuncSetAttribute(k_rq,    cudaFuncAttributeMaxDynamicSharedMemorySize, RQ_SMEM);
    cudaFuncSetAttribute(k_recon, cudaFuncAttributeMaxDynamicSharedMemorySize, RECON_SMEM);

    k_init<<<1, 768>>>();
    k_latent<<<NROWS / 32, 128>>>(emb, Wenc);
    k_rq<<<NROWS / 32, 128, RQ_SMEM>>>(cb0, cb1, cb2);
    k_recon<<<NROWS / 32, 128, RECON_SMEM>>>(emb, Wdec);
    k_finalize<<<1, 768>>>((float*)d_out, out_size);
}

// round 4
// speedup vs baseline: 3.1370x; 3.1370x over previous
#include <cuda_runtime.h>
#include <cuda_bf16.h>
#include <cstdint>

#define NROWS   131072
#define D_IN    512
#define DH      128
#define NCODE   256
#define BETA    0.25

// ---------------- scratch ----------------
__device__ float          g_latent[(size_t)NROWS * DH];
__device__ __nv_bfloat16  g_restored[(size_t)NROWS * DH];
__device__ double g_rq;
__device__ double g_recon;
__device__ int    g_used[3 * NCODE];

// ---------------- helpers ----------------
__device__ __forceinline__ uint32_t s2u(const void* p) {
    uint32_t a;
    asm("{ .reg .u64 t; cvta.to.shared.u64 t, %1; cvt.u32.u64 %0, t; }" : "=r"(a) : "l"(p));
    return a;
}
__device__ __forceinline__ void ldsm4(uint32_t* r, uint32_t addr) {
    asm volatile("ldmatrix.sync.aligned.m8n8.x4.shared.b16 {%0,%1,%2,%3}, [%4];"
        : "=r"(r[0]), "=r"(r[1]), "=r"(r[2]), "=r"(r[3]) : "r"(addr));
}
__device__ __forceinline__ void mma16816(float* c, const uint32_t* a, const uint32_t* b) {
    asm volatile("mma.sync.aligned.m16n8k16.row.col.f32.bf16.bf16.f32 "
        "{%0,%1,%2,%3}, {%4,%5,%6,%7}, {%8,%9}, {%0,%1,%2,%3};"
        : "+f"(c[0]), "+f"(c[1]), "+f"(c[2]), "+f"(c[3])
        : "r"(a[0]), "r"(a[1]), "r"(a[2]), "r"(a[3]), "r"(b[0]), "r"(b[1]));
}
__device__ __forceinline__ void st_bf2(__nv_bfloat16* p, float a, float b) {
    __nv_bfloat162 v = __floats2bfloat162_rn(a, b);
    *(uint32_t*)p = *(uint32_t*)&v;
}

// ---------------- init ----------------
__global__ void k_init() {
    int t = threadIdx.x;
    if (t == 0) { g_rq = 0.0; g_recon = 0.0; }
    if (t < 3 * NCODE) g_used[t] = 0;
}

// =========================================================================
// Kernel A: latent = emb @ Wenc^T.  CTA: 128M x 128N, K=512 in 64-chunks.
// 8 warps (4m x 2n), warp tile 32x64.
// =========================================================================
__global__ __launch_bounds__(256) void k_latent(const float* __restrict__ emb,
                                                const float* __restrict__ Wenc) {
    __shared__ __nv_bfloat16 sA[128 * 72];
    __shared__ __nv_bfloat16 sB[128 * 72];
    int t = threadIdx.x, lane = t & 31, wid = t >> 5;
    int wr = wid >> 1, wc = wid & 1;
    int row0 = blockIdx.x * 128;
    uint32_t aA = s2u(sA), aB = s2u(sB);

    float acc[2][8][4];
#pragma unroll
    for (int mt = 0; mt < 2; mt++)
#pragma unroll
        for (int nt = 0; nt < 8; nt++)
#pragma unroll
            for (int j = 0; j < 4; j++) acc[mt][nt][j] = 0.f;

    for (int c = 0; c < 8; c++) {
        __syncthreads();
#pragma unroll 4
        for (int i = 0; i < 16; i++) {
            int idx = i * 256 + t;
            int row = idx >> 5, cp = idx & 31;
            float2 v = *(const float2*)(emb + (size_t)(row0 + row) * D_IN + c * 64 + cp * 2);
            st_bf2(&sA[row * 72 + cp * 2], v.x, v.y);
            float2 w = *(const float2*)(Wenc + (size_t)row * D_IN + c * 64 + cp * 2);
            st_bf2(&sB[row * 72 + cp * 2], w.x, w.y);
        }
        __syncthreads();
#pragma unroll
        for (int kt = 0; kt < 4; kt++) {
            uint32_t af[2][4], bfr[4][4];
#pragma unroll
            for (int mt = 0; mt < 2; mt++)
                ldsm4(af[mt], aA + ((wr * 32 + mt * 16 + (lane & 15)) * 72
                                    + kt * 16 + (lane >> 4) * 8) * 2);
#pragma unroll
            for (int np = 0; np < 4; np++)
                ldsm4(bfr[np], aB + ((wc * 64 + np * 16 + (lane & 7) + ((lane >> 4) & 1) * 8) * 72
                                     + kt * 16 + ((lane >> 3) & 1) * 8) * 2);
#pragma unroll
            for (int mt = 0; mt < 2; mt++)
#pragma unroll
                for (int np = 0; np < 4; np++) {
                    mma16816(acc[mt][2 * np],     af[mt], &bfr[np][0]);
                    mma16816(acc[mt][2 * np + 1], af[mt], &bfr[np][2]);
                }
        }
    }
#pragma unroll
    for (int mt = 0; mt < 2; mt++)
#pragma unroll
        for (int nt = 0; nt < 8; nt++) {
            int row = row0 + wr * 32 + mt * 16 + (lane >> 2);
            int col = wc * 64 + nt * 8 + (lane & 3) * 2;
            float2 lo = {acc[mt][nt][0], acc[mt][nt][1]};
            float2 hi = {acc[mt][nt][2], acc[mt][nt][3]};
            *(float2*)(g_latent + (size_t)row * DH + col) = lo;
            *(float2*)(g_latent + (size_t)(row + 8) * DH + col) = hi;
        }
}

// =========================================================================
// Kernel B: 3-level residual quantization. CTA: 128 rows, 256 codes, K=128.
// smem (dynamic): sA bf16 128x136 | sCB bf16 256x136 | rem f32 128x132 |
//                 cn f32 256 | bestv f32 2x128 | besti i32 2x128 | idx i32 128
// =========================================================================
#define B_SA   0
#define B_CB   34816
#define B_REM  104448
#define B_CN   172032
#define B_BV   173056
#define B_BI   174080
#define B_IDX  175104
#define B_SMEM 175616
__global__ __launch_bounds__(256) void k_rq(const float* __restrict__ cb0,
                                            const float* __restrict__ cb1,
                                            const float* __restrict__ cb2) {
    extern __shared__ char smc[];
    __nv_bfloat16* sA  = (__nv_bfloat16*)(smc + B_SA);
    __nv_bfloat16* sCB = (__nv_bfloat16*)(smc + B_CB);
    float* rem   = (float*)(smc + B_REM);
    float* cn_s  = (float*)(smc + B_CN);
    float* bestv = (float*)(smc + B_BV);
    int*   besti = (int*)(smc + B_BI);
    int*   idx_s = (int*)(smc + B_IDX);
    uint32_t aSA = s2u(sA), aCB = s2u(sCB);

    int t = threadIdx.x, lane = t & 31, wid = t >> 5;
    int wr = wid >> 1, wc = wid & 1;
    int row0 = blockIdx.x * 128;

    // load latent -> rem fp32 + sA bf16
#pragma unroll 4
    for (int i = 0; i < 32; i++) {
        int idx = i * 256 + t;
        int row = idx >> 6, cp = idx & 63;
        float2 v = *(const float2*)(g_latent + (size_t)(row0 + row) * DH + cp * 2);
        rem[row * 132 + cp * 2] = v.x;
        rem[row * 132 + cp * 2 + 1] = v.y;
        st_bf2(&sA[row * 136 + cp * 2], v.x, v.y);
    }

    float rql = 0.f;
    const float* cbs[3] = {cb0, cb1, cb2};

    for (int L = 0; L < 3; L++) {
        const float* cbg = cbs[L];
        __syncthreads();   // sA/sCB safe to (re)write
        // codebook -> sCB bf16
#pragma unroll 4
        for (int i = 0; i < 64; i++) {
            int idx = i * 256 + t;
            int row = idx >> 6, cp = idx & 63;
            float2 v = *(const float2*)(cbg + (size_t)row * DH + cp * 2);
            st_bf2(&sCB[row * 136 + cp * 2], v.x, v.y);
        }
        // code norms fp32: warp wid -> rows [wid*32, wid*32+32)
        for (int rr = 0; rr < 32; rr++) {
            int r = wid * 32 + rr;
            float4 v = *(const float4*)(cbg + (size_t)r * DH + lane * 4);
            float s = v.x * v.x + v.y * v.y + v.z * v.z + v.w * v.w;
#pragma unroll
            for (int off = 16; off > 0; off >>= 1)
                s += __shfl_xor_sync(0xffffffffu, s, off);
            if (lane == 0) cn_s[r] = s;
        }
        __syncthreads();

        // score + per-thread argmin. rows owned: slot s = mt*2+hi -> row wr*32+mt*16+hi*8+lane/4
        float best[4]; int bidx[4];
#pragma unroll
        for (int s = 0; s < 4; s++) { best[s] = 3.4e38f; bidx[s] = 0; }

        for (int h = 0; h < 2; h++) {
            float acc[2][8][4];
#pragma unroll
            for (int mt = 0; mt < 2; mt++)
#pragma unroll
                for (int nt = 0; nt < 8; nt++)
#pragma unroll
                    for (int j = 0; j < 4; j++) acc[mt][nt][j] = 0.f;
#pragma unroll
            for (int kt = 0; kt < 8; kt++) {
                uint32_t af[2][4], bfr[4][4];
#pragma unroll
                for (int mt = 0; mt < 2; mt++)
                    ldsm4(af[mt], aSA + ((wr * 32 + mt * 16 + (lane & 15)) * 136
                                         + kt * 16 + (lane >> 4) * 8) * 2);
#pragma unroll
                for (int np = 0; np < 4; np++) {
                    int n = h * 128 + wc * 64 + np * 16 + (lane & 7) + ((lane >> 4) & 1) * 8;
                    ldsm4(bfr[np], aCB + (n * 136 + kt * 16 + ((lane >> 3) & 1) * 8) * 2);
                }
#pragma unroll
                for (int mt = 0; mt < 2; mt++)
#pragma unroll
                    for (int np = 0; np < 4; np++) {
                        mma16816(acc[mt][2 * np],     af[mt], &bfr[np][0]);
                        mma16816(acc[mt][2 * np + 1], af[mt], &bfr[np][2]);
                    }
            }
#pragma unroll
            for (int mt = 0; mt < 2; mt++)
#pragma unroll
                for (int nt = 0; nt < 8; nt++) {
                    int col = h * 128 + wc * 64 + nt * 8 + (lane & 3) * 2;
                    float c0 = cn_s[col], c1 = cn_s[col + 1];
#pragma unroll
                    for (int hi = 0; hi < 2; hi++) {
                        int s = mt * 2 + hi;
                        float k0 = c0 - 2.f * acc[mt][nt][hi * 2];
                        float k1 = c1 - 2.f * acc[mt][nt][hi * 2 + 1];
                        if (k0 < best[s]) { best[s] = k0; bidx[s] = col; }
                        if (k1 < best[s]) { best[s] = k1; bidx[s] = col + 1; }
                    }
                }
        }
        // quad reduce + cross-warp combine
#pragma unroll
        for (int s = 0; s < 4; s++) {
            float bv = best[s]; int bi = bidx[s];
#pragma unroll
            for (int off = 1; off < 4; off <<= 1) {
                float ov = __shfl_xor_sync(0xffffffffu, bv, off);
                int   oi = __shfl_xor_sync(0xffffffffu, bi, off);
                if (ov < bv || (ov == bv && oi < bi)) { bv = ov; bi = oi; }
            }
            if ((lane & 3) == 0) {
                int row = wr * 32 + (s >> 1) * 16 + (s & 1) * 8 + (lane >> 2);
                bestv[wc * 128 + row] = bv;
                besti[wc * 128 + row] = bi;
            }
        }
        __syncthreads();
        if (t < 128) {
            float b0 = bestv[t], b1 = bestv[128 + t];
            int i0 = besti[t], i1 = besti[128 + t];
            int ci = (b1 < b0 || (b1 == b0 && i1 < i0)) ? i1 : i0;
            idx_s[t] = ci;
            g_used[L * NCODE + ci] = 1;
        }
        __syncthreads();

        // remainder update (exact fp32 codebook), refresh sA
        for (int i = 0; i < 16; i++) {
            int r = wid * 16 + i;
            int ci = idx_s[r];
            float4 cv = *(const float4*)(cbg + (size_t)ci * DH + lane * 4);
            float4 rv = *(float4*)(rem + r * 132 + lane * 4);
            rv.x -= cv.x; rv.y -= cv.y; rv.z -= cv.z; rv.w -= cv.w;
            rql += rv.x * rv.x + rv.y * rv.y + rv.z * rv.z + rv.w * rv.w;
            *(float4*)(rem + r * 132 + lane * 4) = rv;
            if (L < 2) {
                st_bf2(&sA[r * 136 + lane * 4], rv.x, rv.y);
                st_bf2(&sA[r * 136 + lane * 4 + 2], rv.z, rv.w);
            }
        }
    }
    __syncthreads();

    // restored = latent - rem -> bf16
    uint32_t* rst = (uint32_t*)g_restored;
#pragma unroll 4
    for (int i = 0; i < 32; i++) {
        int idx = i * 256 + t;
        int row = idx >> 6, cp = idx & 63;
        float2 lv = *(const float2*)(g_latent + (size_t)(row0 + row) * DH + cp * 2);
        float a = lv.x - rem[row * 132 + cp * 2];
        float b = lv.y - rem[row * 132 + cp * 2 + 1];
        __nv_bfloat162 p = __floats2bfloat162_rn(a, b);
        rst[(size_t)(row0 + row) * 64 + cp] = *(uint32_t*)&p;
    }

#pragma unroll
    for (int off = 16; off > 0; off >>= 1)
        rql += __shfl_xor_sync(0xffffffffu, rql, off);
    if (lane == 0) atomicAdd(&g_rq, (double)rql);
}

// =========================================================================
// Kernel C: recon MSE. CTA: 128 rows x 512 cols in 4 passes of 128, K=128.
// smem: sA bf16 128x136 | sW bf16 128x136
// =========================================================================
#define C_SMEM 69632
__global__ __launch_bounds__(256) void k_recon(const float* __restrict__ emb,
                                               const float* __restrict__ Wdec) {
    extern __shared__ char smc[];
    __nv_bfloat16* sA = (__nv_bfloat16*)(smc);
    __nv_bfloat16* sW = (__nv_bfloat16*)(smc + 34816);
    uint32_t aSA = s2u(sA), aSW = s2u(sW);
    int t = threadIdx.x, lane = t & 31, wid = t >> 5;
    int wr = wid >> 1, wc = wid & 1;
    int row0 = blockIdx.x * 128;

    const uint32_t* rsv = (const uint32_t*)g_restored;
#pragma unroll 4
    for (int i = 0; i < 32; i++) {
        int idx = i * 256 + t;
        int row = idx >> 6, cp = idx & 63;
        *(uint32_t*)&sA[row * 136 + cp * 2] = rsv[(size_t)(row0 + row) * 64 + cp];
    }

    float local = 0.f;
    for (int p = 0; p < 4; p++) {
        __syncthreads();
#pragma unroll 4
        for (int i = 0; i < 32; i++) {
            int idx = i * 256 + t;
            int row = idx >> 6, cp = idx & 63;
            float2 v = *(const float2*)(Wdec + (size_t)(p * 128 + row) * DH + cp * 2);
            st_bf2(&sW[row * 136 + cp * 2], v.x, v.y);
        }
        __syncthreads();

        float acc[2][8][4];
#pragma unroll
        for (int mt = 0; mt < 2; mt++)
#pragma unroll
            for (int nt = 0; nt < 8; nt++)
#pragma unroll
                for (int j = 0; j < 4; j++) acc[mt][nt][j] = 0.f;
#pragma unroll
        for (int kt = 0; kt < 8; kt++) {
            uint32_t af[2][4], bfr[4][4];
#pragma unroll
            for (int mt = 0; mt < 2; mt++)
                ldsm4(af[mt], aSA + ((wr * 32 + mt * 16 + (lane & 15)) * 136
                                     + kt * 16 + (lane >> 4) * 8) * 2);
#pragma unroll
            for (int np = 0; np < 4; np++) {
                int n = wc * 64 + np * 16 + (lane & 7) + ((lane >> 4) & 1) * 8;
                ldsm4(bfr[np], aSW + (n * 136 + kt * 16 + ((lane >> 3) & 1) * 8) * 2);
            }
#pragma unroll
            for (int mt = 0; mt < 2; mt++)
#pragma unroll
                for (int np = 0; np < 4; np++) {
                    mma16816(acc[mt][2 * np],     af[mt], &bfr[np][0]);
                    mma16816(acc[mt][2 * np + 1], af[mt], &bfr[np][2]);
                }
        }
#pragma unroll
        for (int mt = 0; mt < 2; mt++)
#pragma unroll
            for (int nt = 0; nt < 8; nt++) {
                int row = row0 + wr * 32 + mt * 16 + (lane >> 2);
                int col = p * 128 + wc * 64 + nt * 8 + (lane & 3) * 2;
                float2 e0 = *(const float2*)(emb + (size_t)row * D_IN + col);
                float2 e1 = *(const float2*)(emb + (size_t)(row + 8) * D_IN + col);
                float d0 = acc[mt][nt][0] - e0.x;
                float d1 = acc[mt][nt][1] - e0.y;
                float d2 = acc[mt][nt][2] - e1.x;
                float d3 = acc[mt][nt][3] - e1.y;
                local += d0 * d0 + d1 * d1 + d2 * d2 + d3 * d3;
            }
    }
#pragma unroll
    for (int off = 16; off > 0; off >>= 1)
        local += __shfl_xor_sync(0xffffffffu, local, off);
    if (lane == 0) atomicAdd(&g_recon, (double)local);
}

// ---------------- finalize ----------------
__global__ void k_finalize(float* __restrict__ out, int out_size) {
    __shared__ int cnt[3];
    int t = threadIdx.x;
    if (t < 3) cnt[t] = 0;
    __syncthreads();
    if (t < 3 * NCODE) { if (g_used[t]) atomicAdd(&cnt[t / NCODE], 1); }
    __syncthreads();
    if (t == 0) {
        double recon = g_recon / ((double)NROWS * (double)D_IN);
        double rq    = (1.0 + BETA) * g_rq / ((double)NROWS * (double)DH);
        float rf = (float)recon, qf = (float)rq;
        if (out_size > 0) out[0] = rf + qf;
        if (out_size > 1) out[1] = rf;
        if (out_size > 2) out[2] = qf;
        if (out_size > 3) out[3] = (float)cnt[0];
        if (out_size > 4) out[4] = (float)cnt[1];
        if (out_size > 5) out[5] = (float)cnt[2];
    }
    for (int i = 6 + t; i < out_size; i += blockDim.x) out[i] = 0.f;
}

// ---------------- launch ----------------
extern "C" void kernel_launch(void* const* d_in, const int* in_sizes, int n_in,
                              void* d_out, int out_size) {
    const float* emb  = (const float*)d_in[0];
    const float* Wenc = (const float*)d_in[1];
    const float* Wdec = (const float*)d_in[2];
    const float* cb0  = (const float*)d_in[3];
    const float* cb1  = (const float*)d_in[4];
    const float* cb2  = (const float*)d_in[5];

    cudaFuncSetAttribute(k_rq,    cudaFuncAttributeMaxDynamicSharedMemorySize, B_SMEM);
    cudaFuncSetAttribute(k_recon, cudaFuncAttributeMaxDynamicSharedMemorySize, C_SMEM);

    k_init<<<1, 768>>>();
    k_latent<<<NROWS / 128, 256>>>(emb, Wenc);
    k_rq<<<NROWS / 128, 256, B_SMEM>>>(cb0, cb1, cb2);
    k_recon<<<NROWS / 128, 256, C_SMEM>>>(emb, Wdec);
    k_finalize<<<1, 768>>>((float*)d_out, out_size);
}

// round 5
// speedup vs baseline: 4.5963x; 1.4652x over previous
#include <cuda_runtime.h>
#include <cuda_bf16.h>
#include <cstdint>

#define NROWS   131072
#define D_IN    512
#define DH      128
#define NCODE   256
#define BETA    0.25

// ---------------- scratch ----------------
__device__ float          g_latent[(size_t)NROWS * DH];
__device__ __nv_bfloat16  g_restored[(size_t)NROWS * DH];
__device__ float          g_cn[3 * NCODE];
__device__ double g_rq;
__device__ double g_recon;
__device__ int    g_used[3 * NCODE];

// ---------------- helpers ----------------
__device__ __forceinline__ uint32_t s2u(const void* p) {
    uint32_t a;
    asm("{ .reg .u64 t; cvta.to.shared.u64 t, %1; cvt.u32.u64 %0, t; }" : "=r"(a) : "l"(p));
    return a;
}
__device__ __forceinline__ void ldsm4(uint32_t* r, uint32_t addr) {
    asm volatile("ldmatrix.sync.aligned.m8n8.x4.shared.b16 {%0,%1,%2,%3}, [%4];"
        : "=r"(r[0]), "=r"(r[1]), "=r"(r[2]), "=r"(r[3]) : "r"(addr));
}
__device__ __forceinline__ void mma16816(float* c, const uint32_t* a, const uint32_t* b) {
    asm volatile("mma.sync.aligned.m16n8k16.row.col.f32.bf16.bf16.f32 "
        "{%0,%1,%2,%3}, {%4,%5,%6,%7}, {%8,%9}, {%0,%1,%2,%3};"
        : "+f"(c[0]), "+f"(c[1]), "+f"(c[2]), "+f"(c[3])
        : "r"(a[0]), "r"(a[1]), "r"(a[2]), "r"(a[3]), "r"(b[0]), "r"(b[1]));
}
__device__ __forceinline__ void st_bf2(__nv_bfloat16* p, float a, float b) {
    __nv_bfloat162 v = __floats2bfloat162_rn(a, b);
    *(uint32_t*)p = *(uint32_t*)&v;
}

// ---------------- init + codebook norms ----------------
__global__ void k_init() {
    int t = threadIdx.x;
    if (t == 0) { g_rq = 0.0; g_recon = 0.0; }
    if (t < 3 * NCODE) g_used[t] = 0;
}
__global__ void k_norms(const float* __restrict__ cb0,
                        const float* __restrict__ cb1,
                        const float* __restrict__ cb2) {
    const float* cbs[3] = {cb0, cb1, cb2};
    const float* cb = cbs[blockIdx.x];
    int t = threadIdx.x;
    float s = 0.f;
#pragma unroll
    for (int q = 0; q < 32; q++) {
        float4 v = *(const float4*)(cb + (size_t)t * DH + q * 4);
        s += v.x * v.x + v.y * v.y + v.z * v.z + v.w * v.w;
    }
    g_cn[blockIdx.x * NCODE + t] = s;
}

// =========================================================================
// Kernel A: latent = emb @ Wenc^T.  CTA: 128M x 128N, K=512 in 64-chunks.
// emb chunk prefetched into registers; LDGs overlap MMA of previous chunk.
// =========================================================================
__global__ __launch_bounds__(256, 2) void k_latent(const float* __restrict__ emb,
                                                   const float* __restrict__ Wenc) {
    __shared__ __nv_bfloat16 sA[128 * 72];
    __shared__ __nv_bfloat16 sB[128 * 72];
    int t = threadIdx.x, lane = t & 31, wid = t >> 5;
    int wr = wid >> 1, wc = wid & 1;
    int row0 = blockIdx.x * 128;
    uint32_t aA = s2u(sA), aB = s2u(sB);

    float acc[2][8][4];
#pragma unroll
    for (int mt = 0; mt < 2; mt++)
#pragma unroll
        for (int nt = 0; nt < 8; nt++)
#pragma unroll
            for (int j = 0; j < 4; j++) acc[mt][nt][j] = 0.f;

    int prow = (t * 16) >> 5;            // not used; keep simple indexing below
    (void)prow;

    float2 pe[16];
    // prefetch emb chunk 0
#pragma unroll
    for (int i = 0; i < 16; i++) {
        int idx = i * 256 + t;
        int row = idx >> 5, cp = idx & 31;
        pe[i] = *(const float2*)(emb + (size_t)(row0 + row) * D_IN + cp * 2);
    }

    for (int c = 0; c < 8; c++) {
        __syncthreads();   // previous chunk's MMAs done with smem
#pragma unroll
        for (int i = 0; i < 16; i++) {
            int idx = i * 256 + t;
            int row = idx >> 5, cp = idx & 31;
            st_bf2(&sA[row * 72 + cp * 2], pe[i].x, pe[i].y);
            float2 w = *(const float2*)(Wenc + (size_t)row * D_IN + c * 64 + cp * 2);
            st_bf2(&sB[row * 72 + cp * 2], w.x, w.y);
        }
        __syncthreads();
        // issue next chunk's emb LDGs before MMAs (overlap)
        if (c < 7) {
#pragma unroll
            for (int i = 0; i < 16; i++) {
                int idx = i * 256 + t;
                int row = idx >> 5, cp = idx & 31;
                pe[i] = *(const float2*)(emb + (size_t)(row0 + row) * D_IN + (c + 1) * 64 + cp * 2);
            }
        }
#pragma unroll
        for (int kt = 0; kt < 4; kt++) {
            uint32_t af[2][4], bfr[4][4];
#pragma unroll
            for (int mt = 0; mt < 2; mt++)
                ldsm4(af[mt], aA + ((wr * 32 + mt * 16 + (lane & 15)) * 72
                                    + kt * 16 + (lane >> 4) * 8) * 2);
#pragma unroll
            for (int np = 0; np < 4; np++)
                ldsm4(bfr[np], aB + ((wc * 64 + np * 16 + (lane & 7) + ((lane >> 4) & 1) * 8) * 72
                                     + kt * 16 + ((lane >> 3) & 1) * 8) * 2);
#pragma unroll
            for (int mt = 0; mt < 2; mt++)
#pragma unroll
                for (int np = 0; np < 4; np++) {
                    mma16816(acc[mt][2 * np],     af[mt], &bfr[np][0]);
                    mma16816(acc[mt][2 * np + 1], af[mt], &bfr[np][2]);
                }
        }
    }
#pragma unroll
    for (int mt = 0; mt < 2; mt++)
#pragma unroll
        for (int nt = 0; nt < 8; nt++) {
            int row = row0 + wr * 32 + mt * 16 + (lane >> 2);
            int col = wc * 64 + nt * 8 + (lane & 3) * 2;
            float2 lo = {acc[mt][nt][0], acc[mt][nt][1]};
            float2 hi = {acc[mt][nt][2], acc[mt][nt][3]};
            *(float2*)(g_latent + (size_t)row * DH + col) = lo;
            *(float2*)(g_latent + (size_t)(row + 8) * DH + col) = hi;
        }
}

// =========================================================================
// Kernel B: 3-level residual quantization. Remainder kept ONLY as bf16 sA.
// smem: sA 128x136 bf16 | sCB 256x136 bf16 | cn 256 f32 | bestv/besti | idx
// 105.5KB -> 2 CTAs/SM.
// =========================================================================
#define B_SA   0
#define B_CB   34816
#define B_CN   104448
#define B_BV   105472
#define B_BI   106496
#define B_IDX  107520
#define B_SMEM 108032
__global__ __launch_bounds__(256, 2) void k_rq(const float* __restrict__ cb0,
                                               const float* __restrict__ cb1,
                                               const float* __restrict__ cb2) {
    extern __shared__ char smc[];
    __nv_bfloat16* sA  = (__nv_bfloat16*)(smc + B_SA);
    __nv_bfloat16* sCB = (__nv_bfloat16*)(smc + B_CB);
    float* cn_s  = (float*)(smc + B_CN);
    float* bestv = (float*)(smc + B_BV);
    int*   besti = (int*)(smc + B_BI);
    int*   idx_s = (int*)(smc + B_IDX);
    uint32_t aSA = s2u(sA), aCB = s2u(sCB);

    int t = threadIdx.x, lane = t & 31, wid = t >> 5;
    int wr = wid >> 1, wc = wid & 1;
    int row0 = blockIdx.x * 128;

    // latent -> sA bf16
#pragma unroll 4
    for (int i = 0; i < 32; i++) {
        int idx = i * 256 + t;
        int row = idx >> 6, cp = idx & 63;
        float2 v = *(const float2*)(g_latent + (size_t)(row0 + row) * DH + cp * 2);
        st_bf2(&sA[row * 136 + cp * 2], v.x, v.y);
    }

    float rql = 0.f;
    const float* cbs[3] = {cb0, cb1, cb2};

    for (int L = 0; L < 3; L++) {
        const float* cbg = cbs[L];
        __syncthreads();
        // codebook -> sCB bf16 ; norms from g_cn
#pragma unroll 4
        for (int i = 0; i < 64; i++) {
            int idx = i * 256 + t;
            int row = idx >> 6, cp = idx & 63;
            float2 v = *(const float2*)(cbg + (size_t)row * DH + cp * 2);
            st_bf2(&sCB[row * 136 + cp * 2], v.x, v.y);
        }
        cn_s[t] = g_cn[L * NCODE + t];
        __syncthreads();

        float best[4]; int bidx[4];
#pragma unroll
        for (int s = 0; s < 4; s++) { best[s] = 3.4e38f; bidx[s] = 0; }

        for (int h = 0; h < 2; h++) {
            float acc[2][8][4];
#pragma unroll
            for (int mt = 0; mt < 2; mt++)
#pragma unroll
                for (int nt = 0; nt < 8; nt++)
#pragma unroll
                    for (int j = 0; j < 4; j++) acc[mt][nt][j] = 0.f;
#pragma unroll
            for (int kt = 0; kt < 8; kt++) {
                uint32_t af[2][4], bfr[4][4];
#pragma unroll
                for (int mt = 0; mt < 2; mt++)
                    ldsm4(af[mt], aSA + ((wr * 32 + mt * 16 + (lane & 15)) * 136
                                         + kt * 16 + (lane >> 4) * 8) * 2);
#pragma unroll
                for (int np = 0; np < 4; np++) {
                    int n = h * 128 + wc * 64 + np * 16 + (lane & 7) + ((lane >> 4) & 1) * 8;
                    ldsm4(bfr[np], aCB + (n * 136 + kt * 16 + ((lane >> 3) & 1) * 8) * 2);
                }
#pragma unroll
                for (int mt = 0; mt < 2; mt++)
#pragma unroll
                    for (int np = 0; np < 4; np++) {
                        mma16816(acc[mt][2 * np],     af[mt], &bfr[np][0]);
                        mma16816(acc[mt][2 * np + 1], af[mt], &bfr[np][2]);
                    }
            }
#pragma unroll
            for (int mt = 0; mt < 2; mt++)
#pragma unroll
                for (int nt = 0; nt < 8; nt++) {
                    int col = h * 128 + wc * 64 + nt * 8 + (lane & 3) * 2;
                    float c0 = cn_s[col], c1 = cn_s[col + 1];
#pragma unroll
                    for (int hi = 0; hi < 2; hi++) {
                        int s = mt * 2 + hi;
                        float k0 = c0 - 2.f * acc[mt][nt][hi * 2];
                        float k1 = c1 - 2.f * acc[mt][nt][hi * 2 + 1];
                        if (k0 < best[s]) { best[s] = k0; bidx[s] = col; }
                        if (k1 < best[s]) { best[s] = k1; bidx[s] = col + 1; }
                    }
                }
        }
#pragma unroll
        for (int s = 0; s < 4; s++) {
            float bv = best[s]; int bi = bidx[s];
#pragma unroll
            for (int off = 1; off < 4; off <<= 1) {
                float ov = __shfl_xor_sync(0xffffffffu, bv, off);
                int   oi = __shfl_xor_sync(0xffffffffu, bi, off);
                if (ov < bv || (ov == bv && oi < bi)) { bv = ov; bi = oi; }
            }
            if ((lane & 3) == 0) {
                int row = wr * 32 + (s >> 1) * 16 + (s & 1) * 8 + (lane >> 2);
                bestv[wc * 128 + row] = bv;
                besti[wc * 128 + row] = bi;
            }
        }
        __syncthreads();
        if (t < 128) {
            float b0 = bestv[t], b1 = bestv[128 + t];
            int i0 = besti[t], i1 = besti[128 + t];
            int ci = (b1 < b0 || (b1 == b0 && i1 < i0)) ? i1 : i0;
            idx_s[t] = ci;
            g_used[L * NCODE + ci] = 1;
        }
        __syncthreads();

        // remainder update in fp32 from bf16 rem + fp32 codebook, store bf16
        for (int i = 0; i < 16; i++) {
            int r = wid * 16 + i;
            int ci = idx_s[r];
            float4 cv = *(const float4*)(cbg + (size_t)ci * DH + lane * 4);
            uint32_t p0 = *(uint32_t*)&sA[r * 136 + lane * 4];
            uint32_t p1 = *(uint32_t*)&sA[r * 136 + lane * 4 + 2];
            __nv_bfloat162 b0 = *(__nv_bfloat162*)&p0;
            __nv_bfloat162 b1 = *(__nv_bfloat162*)&p1;
            float n0 = __low2float(b0)  - cv.x;
            float n1 = __high2float(b0) - cv.y;
            float n2 = __low2float(b1)  - cv.z;
            float n3 = __high2float(b1) - cv.w;
            rql += n0 * n0 + n1 * n1 + n2 * n2 + n3 * n3;
            st_bf2(&sA[r * 136 + lane * 4],     n0, n1);
            st_bf2(&sA[r * 136 + lane * 4 + 2], n2, n3);
        }
    }
    __syncthreads();

    // restored = latent - rem_final -> bf16
    uint32_t* rst = (uint32_t*)g_restored;
#pragma unroll 4
    for (int i = 0; i < 32; i++) {
        int idx = i * 256 + t;
        int row = idx >> 6, cp = idx & 63;
        float2 lv = *(const float2*)(g_latent + (size_t)(row0 + row) * DH + cp * 2);
        uint32_t pr = *(uint32_t*)&sA[row * 136 + cp * 2];
        __nv_bfloat162 rb = *(__nv_bfloat162*)&pr;
        float a = lv.x - __low2float(rb);
        float b = lv.y - __high2float(rb);
        __nv_bfloat162 p = __floats2bfloat162_rn(a, b);
        rst[(size_t)(row0 + row) * 64 + cp] = *(uint32_t*)&p;
    }

#pragma unroll
    for (int off = 16; off > 0; off >>= 1)
        rql += __shfl_xor_sync(0xffffffffu, rql, off);
    if (lane == 0) atomicAdd(&g_rq, (double)rql);
}

// =========================================================================
// Kernel C: recon MSE. CTA: 128 rows x 512 cols in 4 passes of 128, K=128.
// =========================================================================
#define C_SMEM 69632
__global__ __launch_bounds__(256, 2) void k_recon(const float* __restrict__ emb,
                                                  const float* __restrict__ Wdec) {
    extern __shared__ char smc[];
    __nv_bfloat16* sA = (__nv_bfloat16*)(smc);
    __nv_bfloat16* sW = (__nv_bfloat16*)(smc + 34816);
    uint32_t aSA = s2u(sA), aSW = s2u(sW);
    int t = threadIdx.x, lane = t & 31, wid = t >> 5;
    int wr = wid >> 1, wc = wid & 1;
    int row0 = blockIdx.x * 128;

    const uint32_t* rsv = (const uint32_t*)g_restored;
#pragma unroll 4
    for (int i = 0; i < 32; i++) {
        int idx = i * 256 + t;
        int row = idx >> 6, cp = idx & 63;
        *(uint32_t*)&sA[row * 136 + cp * 2] = rsv[(size_t)(row0 + row) * 64 + cp];
    }

    float local = 0.f;
    for (int p = 0; p < 4; p++) {
        __syncthreads();
#pragma unroll 4
        for (int i = 0; i < 32; i++) {
            int idx = i * 256 + t;
            int row = idx >> 6, cp = idx & 63;
            float2 v = *(const float2*)(Wdec + (size_t)(p * 128 + row) * DH + cp * 2);
            st_bf2(&sW[row * 136 + cp * 2], v.x, v.y);
        }
        __syncthreads();

        float acc[2][8][4];
#pragma unroll
        for (int mt = 0; mt < 2; mt++)
#pragma unroll
            for (int nt = 0; nt < 8; nt++)
#pragma unroll
                for (int j = 0; j < 4; j++) acc[mt][nt][j] = 0.f;
#pragma unroll
        for (int kt = 0; kt < 8; kt++) {
            uint32_t af[2][4], bfr[4][4];
#pragma unroll
            for (int mt = 0; mt < 2; mt++)
                ldsm4(af[mt], aSA + ((wr * 32 + mt * 16 + (lane & 15)) * 136
                                     + kt * 16 + (lane >> 4) * 8) * 2);
#pragma unroll
            for (int np = 0; np < 4; np++) {
                int n = wc * 64 + np * 16 + (lane & 7) + ((lane >> 4) & 1) * 8;
                ldsm4(bfr[np], aSW + (n * 136 + kt * 16 + ((lane >> 3) & 1) * 8) * 2);
            }
#pragma unroll
            for (int mt = 0; mt < 2; mt++)
#pragma unroll
                for (int np = 0; np < 4; np++) {
                    mma16816(acc[mt][2 * np],     af[mt], &bfr[np][0]);
                    mma16816(acc[mt][2 * np + 1], af[mt], &bfr[np][2]);
                }
        }
#pragma unroll
        for (int mt = 0; mt < 2; mt++)
#pragma unroll
            for (int nt = 0; nt < 8; nt++) {
                int row = row0 + wr * 32 + mt * 16 + (lane >> 2);
                int col = p * 128 + wc * 64 + nt * 8 + (lane & 3) * 2;
                float2 e0 = *(const float2*)(emb + (size_t)row * D_IN + col);
                float2 e1 = *(const float2*)(emb + (size_t)(row + 8) * D_IN + col);
                float d0 = acc[mt][nt][0] - e0.x;
                float d1 = acc[mt][nt][1] - e0.y;
                float d2 = acc[mt][nt][2] - e1.x;
                float d3 = acc[mt][nt][3] - e1.y;
                local += d0 * d0 + d1 * d1 + d2 * d2 + d3 * d3;
            }
    }
#pragma unroll
    for (int off = 16; off > 0; off >>= 1)
        local += __shfl_xor_sync(0xffffffffu, local, off);
    if (lane == 0) atomicAdd(&g_recon, (double)local);
}

// ---------------- finalize ----------------
__global__ void k_finalize(float* __restrict__ out, int out_size) {
    __shared__ int cnt[3];
    int t = threadIdx.x;
    if (t < 3) cnt[t] = 0;
    __syncthreads();
    if (t < 3 * NCODE) { if (g_used[t]) atomicAdd(&cnt[t / NCODE], 1); }
    __syncthreads();
    if (t == 0) {
        double recon = g_recon / ((double)NROWS * (double)D_IN);
        double rq    = (1.0 + BETA) * g_rq / ((double)NROWS * (double)DH);
        float rf = (float)recon, qf = (float)rq;
        if (out_size > 0) out[0] = rf + qf;
        if (out_size > 1) out[1] = rf;
        if (out_size > 2) out[2] = qf;
        if (out_size > 3) out[3] = (float)cnt[0];
        if (out_size > 4) out[4] = (float)cnt[1];
        if (out_size > 5) out[5] = (float)cnt[2];
    }
    for (int i = 6 + t; i < out_size; i += blockDim.x) out[i] = 0.f;
}

// ---------------- launch ----------------
extern "C" void kernel_launch(void* const* d_in, const int* in_sizes, int n_in,
                              void* d_out, int out_size) {
    const float* emb  = (const float*)d_in[0];
    const float* Wenc = (const float*)d_in[1];
    const float* Wdec = (const float*)d_in[2];
    const float* cb0  = (const float*)d_in[3];
    const float* cb1  = (const float*)d_in[4];
    const float* cb2  = (const float*)d_in[5];

    cudaFuncSetAttribute(k_rq,    cudaFuncAttributeMaxDynamicSharedMemorySize, B_SMEM);
    cudaFuncSetAttribute(k_recon, cudaFuncAttributeMaxDynamicSharedMemorySize, C_SMEM);

    k_init<<<1, 768>>>();
    k_norms<<<3, 256>>>(cb0, cb1, cb2);
    k_latent<<<NROWS / 128, 256>>>(emb, Wenc);
    k_rq<<<NROWS / 128, 256, B_SMEM>>>(cb0, cb1, cb2);
    k_recon<<<NROWS / 128, 256, C_SMEM>>>(emb, Wdec);
    k_finalize<<<1, 768>>>((float*)d_out, out_size);
}

// round 6
// speedup vs baseline: 8.1335x; 1.7696x over previous
#include <cuda_runtime.h>
#include <cuda_bf16.h>
#include <cstdint>

#define NROWS   131072
#define D_IN    512
#define DH      128
#define NCODE   256
#define BETA    0.25

// ---------------- scratch ----------------
__device__ float          g_latent[(size_t)NROWS * DH];
__device__ __nv_bfloat16  g_restored[(size_t)NROWS * DH];
__device__ __nv_bfloat16  g_wenc[(size_t)DH * D_IN];      // 128 x 512
__device__ __nv_bfloat16  g_wdec[(size_t)D_IN * DH];      // 512 x 128
__device__ __nv_bfloat16  g_cb[3 * NCODE * DH];           // 3 x 256 x 128
__device__ float          g_cn[3 * NCODE];
__device__ double g_rq;
__device__ double g_recon;
__device__ int    g_used[3 * NCODE];

// ---------------- helpers ----------------
__device__ __forceinline__ uint32_t s2u(const void* p) {
    uint32_t a;
    asm("{ .reg .u64 t; cvta.to.shared.u64 t, %1; cvt.u32.u64 %0, t; }" : "=r"(a) : "l"(p));
    return a;
}
__device__ __forceinline__ void ldsm4(uint32_t* r, uint32_t addr) {
    asm volatile("ldmatrix.sync.aligned.m8n8.x4.shared.b16 {%0,%1,%2,%3}, [%4];"
        : "=r"(r[0]), "=r"(r[1]), "=r"(r[2]), "=r"(r[3]) : "r"(addr));
}
__device__ __forceinline__ void mma16816(float* c, const uint32_t* a, const uint32_t* b) {
    asm volatile("mma.sync.aligned.m16n8k16.row.col.f32.bf16.bf16.f32 "
        "{%0,%1,%2,%3}, {%4,%5,%6,%7}, {%8,%9}, {%0,%1,%2,%3};"
        : "+f"(c[0]), "+f"(c[1]), "+f"(c[2]), "+f"(c[3])
        : "r"(a[0]), "r"(a[1]), "r"(a[2]), "r"(a[3]), "r"(b[0]), "r"(b[1]));
}
__device__ __forceinline__ void st_bf2(__nv_bfloat16* p, float a, float b) {
    __nv_bfloat162 v = __floats2bfloat162_rn(a, b);
    *(uint32_t*)p = *(uint32_t*)&v;
}
__device__ __forceinline__ void cp16(uint32_t dst, const void* src) {
    asm volatile("cp.async.cg.shared.global [%0], [%1], 16;" :: "r"(dst), "l"(src));
}
__device__ __forceinline__ void cp_commit() {
    asm volatile("cp.async.commit_group;" ::: "memory");
}
template<int N> __device__ __forceinline__ void cp_wait() {
    asm volatile("cp.async.wait_group %0;" :: "n"(N) : "memory");
}

// ---------------- init / norms / convert ----------------
__global__ void k_init() {
    int t = threadIdx.x;
    if (t == 0) { g_rq = 0.0; g_recon = 0.0; }
    if (t < 3 * NCODE) g_used[t] = 0;
}
__global__ void k_norms(const float* __restrict__ cb0,
                        const float* __restrict__ cb1,
                        const float* __restrict__ cb2) {
    const float* cbs[3] = {cb0, cb1, cb2};
    const float* cb = cbs[blockIdx.x];
    int t = threadIdx.x;
    float s = 0.f;
#pragma unroll
    for (int q = 0; q < 32; q++) {
        float4 v = *(const float4*)(cb + (size_t)t * DH + q * 4);
        s += v.x * v.x + v.y * v.y + v.z * v.z + v.w * v.w;
    }
    g_cn[blockIdx.x * NCODE + t] = s;
}
// fp32 -> bf16 preconversion: wenc (32768 pairs), wdec (32768), cb0/1/2 (16384 each)
__global__ void k_cvt(const float* __restrict__ we, const float* __restrict__ wd,
                      const float* __restrict__ c0, const float* __restrict__ c1,
                      const float* __restrict__ c2) {
    int i = blockIdx.x * 256 + threadIdx.x;
    const float* src; uint32_t* dst; int off;
    if (i < 32768)       { src = we; dst = (uint32_t*)g_wenc;         off = i; }
    else if (i < 65536)  { src = wd; dst = (uint32_t*)g_wdec;         off = i - 32768; }
    else if (i < 81920)  { src = c0; dst = (uint32_t*)g_cb;           off = i - 65536; }
    else if (i < 98304)  { src = c1; dst = (uint32_t*)g_cb + 16384;   off = i - 81920; }
    else                 { src = c2; dst = (uint32_t*)g_cb + 32768;   off = i - 98304; }
    float2 v = ((const float2*)src)[off];
    __nv_bfloat162 p = __floats2bfloat162_rn(v.x, v.y);
    dst[off] = *(uint32_t*)&p;
}

// =========================================================================
// Kernel A: latent = emb @ Wenc^T.  CTA 128x128, K=512 in 64-chunks.
// Wenc bf16 via double-buffered cp.async; emb via register prefetch.
// smem: sA 18432 | sB0 18432 | sB1 18432  = 55296
// =========================================================================
#define LAT_SMEM 55296
__global__ __launch_bounds__(256, 2) void k_latent(const float* __restrict__ emb) {
    extern __shared__ char smc[];
    __nv_bfloat16* sA = (__nv_bfloat16*)smc;
    uint32_t aA = s2u(smc);
    uint32_t aB[2] = {aA + 18432, aA + 36864};
    int t = threadIdx.x, lane = t & 31, wid = t >> 5;
    int wr = wid >> 1, wc = wid & 1;
    int row0 = blockIdx.x * 128;

    float acc[2][8][4];
#pragma unroll
    for (int mt = 0; mt < 2; mt++)
#pragma unroll
        for (int nt = 0; nt < 8; nt++)
#pragma unroll
            for (int j = 0; j < 4; j++) acc[mt][nt][j] = 0.f;

    // issue Wenc chunk 0 -> sB0
    {
#pragma unroll
        for (int i = 0; i < 4; i++) {
            int q = i * 256 + t;
            int row = q >> 3, c16 = q & 7;
            cp16(aB[0] + row * 144 + c16 * 16, g_wenc + (size_t)row * D_IN + c16 * 8);
        }
        cp_commit();
    }
    // prefetch emb chunk 0
    float2 pe[16];
#pragma unroll
    for (int i = 0; i < 16; i++) {
        int idx = i * 256 + t;
        int row = idx >> 5, cp = idx & 31;
        pe[i] = *(const float2*)(emb + (size_t)(row0 + row) * D_IN + cp * 2);
    }

    for (int c = 0; c < 8; c++) {
        cp_wait<0>();
        __syncthreads();                 // sB[c&1] ready; sA free
        if (c < 7) {
            int buf = (c + 1) & 1;
#pragma unroll
            for (int i = 0; i < 4; i++) {
                int q = i * 256 + t;
                int row = q >> 3, c16 = q & 7;
                cp16(aB[buf] + row * 144 + c16 * 16,
                     g_wenc + (size_t)row * D_IN + (c + 1) * 64 + c16 * 8);
            }
            cp_commit();
        }
#pragma unroll
        for (int i = 0; i < 16; i++) {
            int idx = i * 256 + t;
            int row = idx >> 5, cp = idx & 31;
            st_bf2(&sA[row * 72 + cp * 2], pe[i].x, pe[i].y);
        }
        if (c < 7) {
#pragma unroll
            for (int i = 0; i < 16; i++) {
                int idx = i * 256 + t;
                int row = idx >> 5, cp = idx & 31;
                pe[i] = *(const float2*)(emb + (size_t)(row0 + row) * D_IN + (c + 1) * 64 + cp * 2);
            }
        }
        __syncthreads();
        uint32_t aBc = aB[c & 1];
#pragma unroll
        for (int kt = 0; kt < 4; kt++) {
            uint32_t af[2][4], bfr[4][4];
#pragma unroll
            for (int mt = 0; mt < 2; mt++)
                ldsm4(af[mt], aA + ((wr * 32 + mt * 16 + (lane & 15)) * 72
                                    + kt * 16 + (lane >> 4) * 8) * 2);
#pragma unroll
            for (int np = 0; np < 4; np++)
                ldsm4(bfr[np], aBc + ((wc * 64 + np * 16 + (lane & 7) + ((lane >> 4) & 1) * 8) * 72
                                      + kt * 16 + ((lane >> 3) & 1) * 8) * 2);
#pragma unroll
            for (int mt = 0; mt < 2; mt++)
#pragma unroll
                for (int np = 0; np < 4; np++) {
                    mma16816(acc[mt][2 * np],     af[mt], &bfr[np][0]);
                    mma16816(acc[mt][2 * np + 1], af[mt], &bfr[np][2]);
                }
        }
    }
#pragma unroll
    for (int mt = 0; mt < 2; mt++)
#pragma unroll
        for (int nt = 0; nt < 8; nt++) {
            int row = row0 + wr * 32 + mt * 16 + (lane >> 2);
            int col = wc * 64 + nt * 8 + (lane & 3) * 2;
            float2 lo = {acc[mt][nt][0], acc[mt][nt][1]};
            float2 hi = {acc[mt][nt][2], acc[mt][nt][3]};
            *(float2*)(g_latent + (size_t)row * DH + col) = lo;
            *(float2*)(g_latent + (size_t)(row + 8) * DH + col) = hi;
        }
}

// =========================================================================
// Kernel B: 3-level RQ. Codebooks staged bf16 via cp.async, next level's
// load overlaps argmin/update. Remainder lives as bf16 sA.
// smem: sA 34816 | sCB 69632 | cn 1024 | bestv 1024 | besti 1024 | idx 512
// =========================================================================
#define B_SA   0
#define B_CB   34816
#define B_CN   104448
#define B_BV   105472
#define B_BI   106496
#define B_IDX  107520
#define B_SMEM 108032
__global__ __launch_bounds__(256, 2) void k_rq(const float* __restrict__ cb0,
                                               const float* __restrict__ cb1,
                                               const float* __restrict__ cb2) {
    extern __shared__ char smc[];
    __nv_bfloat16* sA  = (__nv_bfloat16*)(smc + B_SA);
    float* cn_s  = (float*)(smc + B_CN);
    float* bestv = (float*)(smc + B_BV);
    int*   besti = (int*)(smc + B_BI);
    int*   idx_s = (int*)(smc + B_IDX);
    uint32_t aSA = s2u(smc), aCB = aSA + B_CB;

    int t = threadIdx.x, lane = t & 31, wid = t >> 5;
    int wr = wid >> 1, wc = wid & 1;
    int row0 = blockIdx.x * 128;

    // issue codebook 0 -> sCB
    {
#pragma unroll
        for (int i = 0; i < 16; i++) {
            int q = i * 256 + t;
            int row = q >> 4, c16 = q & 15;
            cp16(aCB + row * 272 + c16 * 16, g_cb + (size_t)row * DH + c16 * 8);
        }
        cp_commit();
    }
    // latent -> sA bf16
#pragma unroll 4
    for (int i = 0; i < 32; i++) {
        int idx = i * 256 + t;
        int row = idx >> 6, cp = idx & 63;
        float2 v = *(const float2*)(g_latent + (size_t)(row0 + row) * DH + cp * 2);
        st_bf2(&sA[row * 136 + cp * 2], v.x, v.y);
    }

    float rql = 0.f;
    const float* cbs[3] = {cb0, cb1, cb2};

    for (int L = 0; L < 3; L++) {
        const float* cbg = cbs[L];
        cp_wait<0>();
        cn_s[t] = g_cn[L * NCODE + t];
        __syncthreads();                 // sCB ready, sA current, cn_s visible

        float best[4]; int bidx[4];
#pragma unroll
        for (int s = 0; s < 4; s++) { best[s] = 3.4e38f; bidx[s] = 0; }

        for (int h = 0; h < 2; h++) {
            float acc[2][8][4];
#pragma unroll
            for (int mt = 0; mt < 2; mt++)
#pragma unroll
                for (int nt = 0; nt < 8; nt++)
#pragma unroll
                    for (int j = 0; j < 4; j++) acc[mt][nt][j] = 0.f;
#pragma unroll
            for (int kt = 0; kt < 8; kt++) {
                uint32_t af[2][4], bfr[4][4];
#pragma unroll
                for (int mt = 0; mt < 2; mt++)
                    ldsm4(af[mt], aSA + ((wr * 32 + mt * 16 + (lane & 15)) * 136
                                         + kt * 16 + (lane >> 4) * 8) * 2);
#pragma unroll
                for (int np = 0; np < 4; np++) {
                    int n = h * 128 + wc * 64 + np * 16 + (lane & 7) + ((lane >> 4) & 1) * 8;
                    ldsm4(bfr[np], aCB + (n * 136 + kt * 16 + ((lane >> 3) & 1) * 8) * 2);
                }
#pragma unroll
                for (int mt = 0; mt < 2; mt++)
#pragma unroll
                    for (int np = 0; np < 4; np++) {
                        mma16816(acc[mt][2 * np],     af[mt], &bfr[np][0]);
                        mma16816(acc[mt][2 * np + 1], af[mt], &bfr[np][2]);
                    }
            }
#pragma unroll
            for (int mt = 0; mt < 2; mt++)
#pragma unroll
                for (int nt = 0; nt < 8; nt++) {
                    int col = h * 128 + wc * 64 + nt * 8 + (lane & 3) * 2;
                    float c0 = cn_s[col], c1 = cn_s[col + 1];
#pragma unroll
                    for (int hi = 0; hi < 2; hi++) {
                        int s = mt * 2 + hi;
                        float k0 = fmaf(-2.f, acc[mt][nt][hi * 2],     c0);
                        float k1 = fmaf(-2.f, acc[mt][nt][hi * 2 + 1], c1);
                        if (k0 < best[s]) { best[s] = k0; bidx[s] = col; }
                        if (k1 < best[s]) { best[s] = k1; bidx[s] = col + 1; }
                    }
                }
        }
        __syncthreads();                 // all done reading sCB
        if (L < 2) {                     // overlap next codebook load with argmin/update
#pragma unroll
            for (int i = 0; i < 16; i++) {
                int q = i * 256 + t;
                int row = q >> 4, c16 = q & 15;
                cp16(aCB + row * 272 + c16 * 16,
                     g_cb + (size_t)(L + 1) * NCODE * DH + (size_t)row * DH + c16 * 8);
            }
            cp_commit();
        }
#pragma unroll
        for (int s = 0; s < 4; s++) {
            float bv = best[s]; int bi = bidx[s];
#pragma unroll
            for (int off = 1; off < 4; off <<= 1) {
                float ov = __shfl_xor_sync(0xffffffffu, bv, off);
                int   oi = __shfl_xor_sync(0xffffffffu, bi, off);
                if (ov < bv || (ov == bv && oi < bi)) { bv = ov; bi = oi; }
            }
            if ((lane & 3) == 0) {
                int row = wr * 32 + (s >> 1) * 16 + (s & 1) * 8 + (lane >> 2);
                bestv[wc * 128 + row] = bv;
                besti[wc * 128 + row] = bi;
            }
        }
        __syncthreads();
        if (t < 128) {
            float b0 = bestv[t], b1 = bestv[128 + t];
            int i0 = besti[t], i1 = besti[128 + t];
            int ci = (b1 < b0 || (b1 == b0 && i1 < i0)) ? i1 : i0;
            idx_s[t] = ci;
            g_used[L * NCODE + ci] = 1;
        }
        __syncthreads();

        // remainder update: fp32 codebook gather, bf16 store back
        for (int i = 0; i < 16; i++) {
            int r = wid * 16 + i;
            int ci = idx_s[r];
            float4 cv = *(const float4*)(cbg + (size_t)ci * DH + lane * 4);
            uint32_t p0 = *(uint32_t*)&sA[r * 136 + lane * 4];
            uint32_t p1 = *(uint32_t*)&sA[r * 136 + lane * 4 + 2];
            __nv_bfloat162 b0 = *(__nv_bfloat162*)&p0;
            __nv_bfloat162 b1 = *(__nv_bfloat162*)&p1;
            float n0 = __low2float(b0)  - cv.x;
            float n1 = __high2float(b0) - cv.y;
            float n2 = __low2float(b1)  - cv.z;
            float n3 = __high2float(b1) - cv.w;
            rql += n0 * n0 + n1 * n1 + n2 * n2 + n3 * n3;
            st_bf2(&sA[r * 136 + lane * 4],     n0, n1);
            st_bf2(&sA[r * 136 + lane * 4 + 2], n2, n3);
        }
    }
    __syncthreads();

    // restored = latent - rem_final -> bf16
    uint32_t* rst = (uint32_t*)g_restored;
#pragma unroll 4
    for (int i = 0; i < 32; i++) {
        int idx = i * 256 + t;
        int row = idx >> 6, cp = idx & 63;
        float2 lv = *(const float2*)(g_latent + (size_t)(row0 + row) * DH + cp * 2);
        uint32_t pr = *(uint32_t*)&sA[row * 136 + cp * 2];
        __nv_bfloat162 rb = *(__nv_bfloat162*)&pr;
        float a = lv.x - __low2float(rb);
        float b = lv.y - __high2float(rb);
        __nv_bfloat162 p = __floats2bfloat162_rn(a, b);
        rst[(size_t)(row0 + row) * 64 + cp] = *(uint32_t*)&p;
    }

#pragma unroll
    for (int off = 16; off > 0; off >>= 1)
        rql += __shfl_xor_sync(0xffffffffu, rql, off);
    if (lane == 0) atomicAdd(&g_rq, (double)rql);
}

// =========================================================================
// Kernel C: recon MSE. CTA 128 rows x 512 cols (4 passes), K=128.
// restored + Wdec staged via cp.async (Wdec double-buffered).
// smem: sA 34816 | sW0 34816 | sW1 34816 = 104448
// =========================================================================
#define C_SMEM 104448
__global__ __launch_bounds__(256, 2) void k_recon(const float* __restrict__ emb) {
    extern __shared__ char smc[];
    uint32_t aSA = s2u(smc);
    uint32_t aW[2] = {aSA + 34816, aSA + 69632};
    int t = threadIdx.x, lane = t & 31, wid = t >> 5;
    int wr = wid >> 1, wc = wid & 1;
    int row0 = blockIdx.x * 128;

    // issue restored tile + Wdec pass 0
    {
#pragma unroll
        for (int i = 0; i < 8; i++) {
            int q = i * 256 + t;
            int row = q >> 4, c16 = q & 15;
            cp16(aSA + row * 272 + c16 * 16,
                 g_restored + (size_t)(row0 + row) * DH + c16 * 8);
        }
        cp_commit();
#pragma unroll
        for (int i = 0; i < 8; i++) {
            int q = i * 256 + t;
            int row = q >> 4, c16 = q & 15;
            cp16(aW[0] + row * 272 + c16 * 16, g_wdec + (size_t)row * DH + c16 * 8);
        }
        cp_commit();
    }

    float local = 0.f;
    for (int p = 0; p < 4; p++) {
        cp_wait<0>();
        __syncthreads();
        if (p < 3) {
            int buf = (p + 1) & 1;
#pragma unroll
            for (int i = 0; i < 8; i++) {
                int q = i * 256 + t;
                int row = q >> 4, c16 = q & 15;
                cp16(aW[buf] + row * 272 + c16 * 16,
                     g_wdec + (size_t)((p + 1) * 128 + row) * DH + c16 * 8);
            }
            cp_commit();
        }
        uint32_t aWc = aW[p & 1];

        float acc[2][8][4];
#pragma unroll
        for (int mt = 0; mt < 2; mt++)
#pragma unroll
            for (int nt = 0; nt < 8; nt++)
#pragma unroll
                for (int j = 0; j < 4; j++) acc[mt][nt][j] = 0.f;
#pragma unroll
        for (int kt = 0; kt < 8; kt++) {
            uint32_t af[2][4], bfr[4][4];
#pragma unroll
            for (int mt = 0; mt < 2; mt++)
                ldsm4(af[mt], aSA + ((wr * 32 + mt * 16 + (lane & 15)) * 136
                                     + kt * 16 + (lane >> 4) * 8) * 2);
#pragma unroll
            for (int np = 0; np < 4; np++) {
                int n = wc * 64 + np * 16 + (lane & 7) + ((lane >> 4) & 1) * 8;
                ldsm4(bfr[np], aWc + (n * 136 + kt * 16 + ((lane >> 3) & 1) * 8) * 2);
            }
#pragma unroll
            for (int mt = 0; mt < 2; mt++)
#pragma unroll
                for (int np = 0; np < 4; np++) {
                    mma16816(acc[mt][2 * np],     af[mt], &bfr[np][0]);
                    mma16816(acc[mt][2 * np + 1], af[mt], &bfr[np][2]);
                }
        }
#pragma unroll
        for (int mt = 0; mt < 2; mt++)
#pragma unroll
            for (int nt = 0; nt < 8; nt++) {
                int row = row0 + wr * 32 + mt * 16 + (lane >> 2);
                int col = p * 128 + wc * 64 + nt * 8 + (lane & 3) * 2;
                float2 e0 = *(const float2*)(emb + (size_t)row * D_IN + col);
                float2 e1 = *(const float2*)(emb + (size_t)(row + 8) * D_IN + col);
                float d0 = acc[mt][nt][0] - e0.x;
                float d1 = acc[mt][nt][1] - e0.y;
                float d2 = acc[mt][nt][2] - e1.x;
                float d3 = acc[mt][nt][3] - e1.y;
                local += d0 * d0 + d1 * d1 + d2 * d2 + d3 * d3;
            }
    }
#pragma unroll
    for (int off = 16; off > 0; off >>= 1)
        local += __shfl_xor_sync(0xffffffffu, local, off);
    if (lane == 0) atomicAdd(&g_recon, (double)local);
}

// ---------------- finalize ----------------
__global__ void k_finalize(float* __restrict__ out, int out_size) {
    __shared__ int cnt[3];
    int t = threadIdx.x;
    if (t < 3) cnt[t] = 0;
    __syncthreads();
    if (t < 3 * NCODE) { if (g_used[t]) atomicAdd(&cnt[t / NCODE], 1); }
    __syncthreads();
    if (t == 0) {
        double recon = g_recon / ((double)NROWS * (double)D_IN);
        double rq    = (1.0 + BETA) * g_rq / ((double)NROWS * (double)DH);
        float rf = (float)recon, qf = (float)rq;
        if (out_size > 0) out[0] = rf + qf;
        if (out_size > 1) out[1] = rf;
        if (out_size > 2) out[2] = qf;
        if (out_size > 3) out[3] = (float)cnt[0];
        if (out_size > 4) out[4] = (float)cnt[1];
        if (out_size > 5) out[5] = (float)cnt[2];
    }
    for (int i = 6 + t; i < out_size; i += blockDim.x) out[i] = 0.f;
}

// ---------------- launch ----------------
extern "C" void kernel_launch(void* const* d_in, const int* in_sizes, int n_in,
                              void* d_out, int out_size) {
    const float* emb  = (const float*)d_in[0];
    const float* Wenc = (const float*)d_in[1];
    const float* Wdec = (const float*)d_in[2];
    const float* cb0  = (const float*)d_in[3];
    const float* cb1  = (const float*)d_in[4];
    const float* cb2  = (const float*)d_in[5];

    cudaFuncSetAttribute(k_latent, cudaFuncAttributeMaxDynamicSharedMemorySize, LAT_SMEM);
    cudaFuncSetAttribute(k_rq,     cudaFuncAttributeMaxDynamicSharedMemorySize, B_SMEM);
    cudaFuncSetAttribute(k_recon,  cudaFuncAttributeMaxDynamicSharedMemorySize, C_SMEM);

    k_init<<<1, 768>>>();
    k_norms<<<3, 256>>>(cb0, cb1, cb2);
    k_cvt<<<448, 256>>>(Wenc, Wdec, cb0, cb1, cb2);
    k_latent<<<NROWS / 128, 256, LAT_SMEM>>>(emb);
    k_rq<<<NROWS / 128, 256, B_SMEM>>>(cb0, cb1, cb2);
    k_recon<<<NROWS / 128, 256, C_SMEM>>>(emb);
    k_finalize<<<1, 768>>>((float*)d_out, out_size);
}

// round 8
// speedup vs baseline: 8.6326x; 1.0614x over previous
#include <cuda_runtime.h>
#include <cuda_bf16.h>
#include <cstdint>

#define NROWS   131072
#define D_IN    512
#define DH      128
#define NCODE   256
#define BETA    0.25

// ---------------- scratch ----------------
__device__ __nv_bfloat16  g_wenc[(size_t)DH * D_IN];      // 128 x 512
__device__ __nv_bfloat16  g_wdec[(size_t)D_IN * DH];      // 512 x 128
__device__ __nv_bfloat16  g_cb[3 * NCODE * DH];           // 3 x 256 x 128
__device__ float          g_cn[3 * NCODE];
__device__ double g_rq;
__device__ double g_recon;
__device__ int    g_used[3 * NCODE];

// ---------------- helpers ----------------
__device__ __forceinline__ uint32_t s2u(const void* p) {
    uint32_t a;
    asm("{ .reg .u64 t; cvta.to.shared.u64 t, %1; cvt.u32.u64 %0, t; }" : "=r"(a) : "l"(p));
    return a;
}
__device__ __forceinline__ void ldsm4(uint32_t* r, uint32_t addr) {
    asm volatile("ldmatrix.sync.aligned.m8n8.x4.shared.b16 {%0,%1,%2,%3}, [%4];"
        : "=r"(r[0]), "=r"(r[1]), "=r"(r[2]), "=r"(r[3]) : "r"(addr));
}
__device__ __forceinline__ void mma16816(float* c, const uint32_t* a, const uint32_t* b) {
    asm volatile("mma.sync.aligned.m16n8k16.row.col.f32.bf16.bf16.f32 "
        "{%0,%1,%2,%3}, {%4,%5,%6,%7}, {%8,%9}, {%0,%1,%2,%3};"
        : "+f"(c[0]), "+f"(c[1]), "+f"(c[2]), "+f"(c[3])
        : "r"(a[0]), "r"(a[1]), "r"(a[2]), "r"(a[3]), "r"(b[0]), "r"(b[1]));
}
__device__ __forceinline__ void st_bf2(__nv_bfloat16* p, float a, float b) {
    __nv_bfloat162 v = __floats2bfloat162_rn(a, b);
    *(uint32_t*)p = *(uint32_t*)&v;
}
__device__ __forceinline__ void cp16(uint32_t dst, const void* src) {
    asm volatile("cp.async.cg.shared.global [%0], [%1], 16;" :: "r"(dst), "l"(src));
}
__device__ __forceinline__ void cp_commit() {
    asm volatile("cp.async.commit_group;" ::: "memory");
}
template<int N> __device__ __forceinline__ void cp_wait() {
    asm volatile("cp.async.wait_group %0;" :: "n"(N) : "memory");
}

// ---------------- init / norms / convert ----------------
__global__ void k_init() {
    int t = threadIdx.x;
    if (t == 0) { g_rq = 0.0; g_recon = 0.0; }
    if (t < 3 * NCODE) g_used[t] = 0;
}
__global__ void k_norms(const float* __restrict__ cb0,
                        const float* __restrict__ cb1,
                        const float* __restrict__ cb2) {
    const float* cbs[3] = {cb0, cb1, cb2};
    const float* cb = cbs[blockIdx.x];
    int t = threadIdx.x;
    float s = 0.f;
#pragma unroll
    for (int q = 0; q < 32; q++) {
        float4 v = *(const float4*)(cb + (size_t)t * DH + q * 4);
        s += v.x * v.x + v.y * v.y + v.z * v.z + v.w * v.w;
    }
    g_cn[blockIdx.x * NCODE + t] = s;
}
__global__ void k_cvt(const float* __restrict__ we, const float* __restrict__ wd,
                      const float* __restrict__ c0, const float* __restrict__ c1,
                      const float* __restrict__ c2) {
    int i = blockIdx.x * 256 + threadIdx.x;
    const float* src; uint32_t* dst; int off;
    if (i < 32768)       { src = we; dst = (uint32_t*)g_wenc;         off = i; }
    else if (i < 65536)  { src = wd; dst = (uint32_t*)g_wdec;         off = i - 32768; }
    else if (i < 81920)  { src = c0; dst = (uint32_t*)g_cb;           off = i - 65536; }
    else if (i < 98304)  { src = c1; dst = (uint32_t*)g_cb + 16384;   off = i - 81920; }
    else                 { src = c2; dst = (uint32_t*)g_cb + 32768;   off = i - 98304; }
    float2 v = ((const float2*)src)[off];
    __nv_bfloat162 p = __floats2bfloat162_rn(v.x, v.y);
    dst[off] = *(uint32_t*)&p;
}

// =========================================================================
// Fused kernel: GEMM1 + 3-level RQ + recon GEMM + MSE. 512 thr, 128 rows/CTA.
// smem map (bytes):
//  sA (rem bf16, 128x136)        @ 0       34816
//  sR (restored bf16, 128x136)   @ 34816   34816
//  sCB (codebook bf16, 256x136)  @ 69632   69632
//  sSTG (staging)                @ 139264  69632
//     GEMM1: emb chunk (128x72) @+0, wenc buf0 @+18432, buf1 @+36864
//     recon: wdec buf0 (128x136) @+0, buf1 @+34816
//  cn f32[256]                   @ 208896  1024
//  bestv f32[4][128]             @ 209920  2048
//  besti i32[4][128]             @ 211968  2048
//  idx i32[128]                  @ 214016  512
// total 214528
// =========================================================================
#define F_SA   0
#define F_SR   34816
#define F_CB   69632
#define F_STG  139264
#define F_CN   208896
#define F_BV   209920
#define F_BI   211968
#define F_IDX  214016
#define F_SMEM 214528

__global__ __launch_bounds__(512, 1) void k_fused(const float* __restrict__ emb,
                                                  const float* __restrict__ cb0,
                                                  const float* __restrict__ cb1,
                                                  const float* __restrict__ cb2) {
    extern __shared__ char smc[];
    __nv_bfloat16* sA = (__nv_bfloat16*)(smc + F_SA);
    __nv_bfloat16* sR = (__nv_bfloat16*)(smc + F_SR);
    __nv_bfloat16* sE = (__nv_bfloat16*)(smc + F_STG);
    float* cn_s  = (float*)(smc + F_CN);
    float* bestv = (float*)(smc + F_BV);
    int*   besti = (int*)(smc + F_BI);
    int*   idx_s = (int*)(smc + F_IDX);
    uint32_t aBase = s2u(smc);
    uint32_t aSA = aBase + F_SA, aSR = aBase + F_SR, aCB = aBase + F_CB;
    uint32_t aE = aBase + F_STG;
    uint32_t aW[2] = {aE + 18432, aE + 36864};          // GEMM1 wenc bufs
    uint32_t aD[2] = {aE, aE + 34816};                  // recon wdec bufs

    int t = threadIdx.x, lane = t & 31, wid = t >> 5;
    int wr = wid >> 2, wc = wid & 3;
    int row0 = blockIdx.x * 128;

    // ---- issue codebook 0 + wenc chunk 0 ----
#pragma unroll
    for (int i = 0; i < 8; i++) {
        int q = i * 512 + t;
        int row = q >> 4, c16 = q & 15;
        cp16(aCB + row * 272 + c16 * 16, g_cb + (size_t)row * DH + c16 * 8);
    }
    cp_commit();
#pragma unroll
    for (int i = 0; i < 2; i++) {
        int q = i * 512 + t;
        int row = q >> 3, c16 = q & 7;
        cp16(aW[0] + row * 144 + c16 * 16, g_wenc + (size_t)row * D_IN + c16 * 8);
    }
    cp_commit();

    // ---- emb chunk 0 register prefetch ----
    float2 pe[8];
#pragma unroll
    for (int i = 0; i < 8; i++) {
        int idx = i * 512 + t;
        int row = idx >> 5, cp = idx & 31;
        pe[i] = *(const float2*)(emb + (size_t)(row0 + row) * D_IN + cp * 2);
    }

    // =========== Phase 1: latent = emb @ Wenc^T (acc in regs) ===========
    float acc1[2][4][4];
#pragma unroll
    for (int mt = 0; mt < 2; mt++)
#pragma unroll
        for (int nt = 0; nt < 4; nt++)
#pragma unroll
            for (int j = 0; j < 4; j++) acc1[mt][nt][j] = 0.f;

    for (int c = 0; c < 8; c++) {
        cp_wait<0>();
        __syncthreads();
        if (c < 7) {
            int buf = (c + 1) & 1;
#pragma unroll
            for (int i = 0; i < 2; i++) {
                int q = i * 512 + t;
                int row = q >> 3, c16 = q & 7;
                cp16(aW[buf] + row * 144 + c16 * 16,
                     g_wenc + (size_t)row * D_IN + (c + 1) * 64 + c16 * 8);
            }
            cp_commit();
        }
#pragma unroll
        for (int i = 0; i < 8; i++) {
            int idx = i * 512 + t;
            int row = idx >> 5, cp = idx & 31;
            st_bf2(&sE[row * 72 + cp * 2], pe[i].x, pe[i].y);
        }
        if (c < 7) {
#pragma unroll
            for (int i = 0; i < 8; i++) {
                int idx = i * 512 + t;
                int row = idx >> 5, cp = idx & 31;
                pe[i] = *(const float2*)(emb + (size_t)(row0 + row) * D_IN + (c + 1) * 64 + cp * 2);
            }
        }
        __syncthreads();
        uint32_t aWc = aW[c & 1];
#pragma unroll
        for (int kt = 0; kt < 4; kt++) {
            uint32_t af[2][4], bfr[2][4];
#pragma unroll
            for (int mt = 0; mt < 2; mt++)
                ldsm4(af[mt], aE + ((wr * 32 + mt * 16 + (lane & 15)) * 72
                                    + kt * 16 + (lane >> 4) * 8) * 2);
#pragma unroll
            for (int np = 0; np < 2; np++) {
                int n = wc * 32 + np * 16 + (lane & 7) + ((lane >> 4) & 1) * 8;
                ldsm4(bfr[np], aWc + (n * 72 + kt * 16 + ((lane >> 3) & 1) * 8) * 2);
            }
#pragma unroll
            for (int mt = 0; mt < 2; mt++)
#pragma unroll
                for (int np = 0; np < 2; np++) {
                    mma16816(acc1[mt][2 * np],     af[mt], &bfr[np][0]);
                    mma16816(acc1[mt][2 * np + 1], af[mt], &bfr[np][2]);
                }
        }
    }
    // latent -> sA (bf16 remainder seed)
    __syncthreads();
#pragma unroll
    for (int mt = 0; mt < 2; mt++)
#pragma unroll
        for (int nt = 0; nt < 4; nt++) {
            int row = wr * 32 + mt * 16 + (lane >> 2);
            int col = wc * 32 + nt * 8 + (lane & 3) * 2;
            st_bf2(&sA[row * 136 + col],       acc1[mt][nt][0], acc1[mt][nt][1]);
            st_bf2(&sA[(row + 8) * 136 + col], acc1[mt][nt][2], acc1[mt][nt][3]);
        }

    // =========== Phase 2: 3-level residual quantization ===========
    float rql = 0.f;
    const float* cbs[3] = {cb0, cb1, cb2};

    for (int L = 0; L < 3; L++) {
        const float* cbg = cbs[L];
        cp_wait<0>();
        if (t < 256) cn_s[t] = g_cn[L * NCODE + t];
        __syncthreads();        // sA current, sCB ready, cn_s visible

        float best[4]; int bidx[4];
#pragma unroll
        for (int s = 0; s < 4; s++) { best[s] = 3.4e38f; bidx[s] = 0; }

        float acc[2][8][4];
#pragma unroll
        for (int mt = 0; mt < 2; mt++)
#pragma unroll
            for (int nt = 0; nt < 8; nt++)
#pragma unroll
                for (int j = 0; j < 4; j++) acc[mt][nt][j] = 0.f;
#pragma unroll
        for (int kt = 0; kt < 8; kt++) {
            uint32_t af[2][4], bfr[4][4];
#pragma unroll
            for (int mt = 0; mt < 2; mt++)
                ldsm4(af[mt], aSA + ((wr * 32 + mt * 16 + (lane & 15)) * 136
                                     + kt * 16 + (lane >> 4) * 8) * 2);
#pragma unroll
            for (int np = 0; np < 4; np++) {
                int n = wc * 64 + np * 16 + (lane & 7) + ((lane >> 4) & 1) * 8;
                ldsm4(bfr[np], aCB + (n * 136 + kt * 16 + ((lane >> 3) & 1) * 8) * 2);
            }
#pragma unroll
            for (int mt = 0; mt < 2; mt++)
#pragma unroll
                for (int np = 0; np < 4; np++) {
                    mma16816(acc[mt][2 * np],     af[mt], &bfr[np][0]);
                    mma16816(acc[mt][2 * np + 1], af[mt], &bfr[np][2]);
                }
        }
#pragma unroll
        for (int mt = 0; mt < 2; mt++)
#pragma unroll
            for (int nt = 0; nt < 8; nt++) {
                int col = wc * 64 + nt * 8 + (lane & 3) * 2;
                float c0 = cn_s[col], c1 = cn_s[col + 1];
#pragma unroll
                for (int hi = 0; hi < 2; hi++) {
                    int s = mt * 2 + hi;
                    float k0 = fmaf(-2.f, acc[mt][nt][hi * 2],     c0);
                    float k1 = fmaf(-2.f, acc[mt][nt][hi * 2 + 1], c1);
                    if (k0 < best[s]) { best[s] = k0; bidx[s] = col; }
                    if (k1 < best[s]) { best[s] = k1; bidx[s] = col + 1; }
                }
            }
        __syncthreads();        // all warps done reading sCB
        if (L < 2) {            // overlap next codebook load
#pragma unroll
            for (int i = 0; i < 8; i++) {
                int q = i * 512 + t;
                int row = q >> 4, c16 = q & 15;
                cp16(aCB + row * 272 + c16 * 16,
                     g_cb + (size_t)(L + 1) * NCODE * DH + (size_t)row * DH + c16 * 8);
            }
            cp_commit();
        } else {                // overlap Wdec pass-0 load
#pragma unroll
            for (int i = 0; i < 4; i++) {
                int q = i * 512 + t;
                int row = q >> 4, c16 = q & 15;
                cp16(aD[0] + row * 272 + c16 * 16, g_wdec + (size_t)row * DH + c16 * 8);
            }
            cp_commit();
        }
#pragma unroll
        for (int s = 0; s < 4; s++) {
            float bv = best[s]; int bi = bidx[s];
#pragma unroll
            for (int off = 1; off < 4; off <<= 1) {
                float ov = __shfl_xor_sync(0xffffffffu, bv, off);
                int   oi = __shfl_xor_sync(0xffffffffu, bi, off);
                if (ov < bv || (ov == bv && oi < bi)) { bv = ov; bi = oi; }
            }
            if ((lane & 3) == 0) {
                int row = wr * 32 + (s >> 1) * 16 + (s & 1) * 8 + (lane >> 2);
                bestv[wc * 128 + row] = bv;
                besti[wc * 128 + row] = bi;
            }
        }
        __syncthreads();
        if (t < 128) {
            float bv = bestv[t]; int bi = besti[t];
#pragma unroll
            for (int w = 1; w < 4; w++) {
                float ov = bestv[w * 128 + t]; int oi = besti[w * 128 + t];
                if (ov < bv || (ov == bv && oi < bi)) { bv = ov; bi = oi; }
            }
            idx_s[t] = bi;
            g_used[L * NCODE + bi] = 1;
        }
        __syncthreads();

        // remainder + restored update (fp32 codebook gather)
#pragma unroll
        for (int i = 0; i < 8; i++) {
            int r = wid * 8 + i;
            int ci = idx_s[r];
            float4 cv = *(const float4*)(cbg + (size_t)ci * DH + lane * 4);
            uint32_t p0 = *(uint32_t*)&sA[r * 136 + lane * 4];
            uint32_t p1 = *(uint32_t*)&sA[r * 136 + lane * 4 + 2];
            __nv_bfloat162 b0 = *(__nv_bfloat162*)&p0;
            __nv_bfloat162 b1 = *(__nv_bfloat162*)&p1;
            float n0 = __low2float(b0)  - cv.x;
            float n1 = __high2float(b0) - cv.y;
            float n2 = __low2float(b1)  - cv.z;
            float n3 = __high2float(b1) - cv.w;
            rql += n0 * n0 + n1 * n1 + n2 * n2 + n3 * n3;
            st_bf2(&sA[r * 136 + lane * 4],     n0, n1);
            st_bf2(&sA[r * 136 + lane * 4 + 2], n2, n3);
            float r0 = cv.x, r1 = cv.y, r2 = cv.z, r3 = cv.w;
            if (L > 0) {
                uint32_t q0 = *(uint32_t*)&sR[r * 136 + lane * 4];
                uint32_t q1 = *(uint32_t*)&sR[r * 136 + lane * 4 + 2];
                __nv_bfloat162 rb0 = *(__nv_bfloat162*)&q0;
                __nv_bfloat162 rb1 = *(__nv_bfloat162*)&q1;
                r0 += __low2float(rb0);  r1 += __high2float(rb0);
                r2 += __low2float(rb1);  r3 += __high2float(rb1);
            }
            st_bf2(&sR[r * 136 + lane * 4],     r0, r1);
            st_bf2(&sR[r * 136 + lane * 4 + 2], r2, r3);
        }
    }

    // =========== Phase 3: recon GEMM + fused MSE ===========
    float local = 0.f;
    for (int p = 0; p < 4; p++) {
        cp_wait<0>();
        __syncthreads();        // wdec buf ready; prior pass done reading other buf
        if (p < 3) {
            int buf = (p + 1) & 1;
#pragma unroll
            for (int i = 0; i < 4; i++) {
                int q = i * 512 + t;
                int row = q >> 4, c16 = q & 15;
                cp16(aD[buf] + row * 272 + c16 * 16,
                     g_wdec + (size_t)((p + 1) * 128 + row) * DH + c16 * 8);
            }
            cp_commit();
        }
        uint32_t aDc = aD[p & 1];
        float accR[2][4][4];
#pragma unroll
        for (int mt = 0; mt < 2; mt++)
#pragma unroll
            for (int nt = 0; nt < 4; nt++)
#pragma unroll
                for (int j = 0; j < 4; j++) accR[mt][nt][j] = 0.f;
#pragma unroll
        for (int kt = 0; kt < 8; kt++) {
            uint32_t af[2][4], bfr[2][4];
#pragma unroll
            for (int mt = 0; mt < 2; mt++)
                ldsm4(af[mt], aSR + ((wr * 32 + mt * 16 + (lane & 15)) * 136
                                     + kt * 16 + (lane >> 4) * 8) * 2);
#pragma unroll
            for (int np = 0; np < 2; np++) {
                int n = wc * 32 + np * 16 + (lane & 7) + ((lane >> 4) & 1) * 8;
                ldsm4(bfr[np], aDc + (n * 136 + kt * 16 + ((lane >> 3) & 1) * 8) * 2);
            }
#pragma unroll
            for (int mt = 0; mt < 2; mt++)
#pragma unroll
                for (int np = 0; np < 2; np++) {
                    mma16816(accR[mt][2 * np],     af[mt], &bfr[np][0]);
                    mma16816(accR[mt][2 * np + 1], af[mt], &bfr[np][2]);
                }
        }
#pragma unroll
        for (int mt = 0; mt < 2; mt++)
#pragma unroll
            for (int nt = 0; nt < 4; nt++) {
                int row = row0 + wr * 32 + mt * 16 + (lane >> 2);
                int col = p * 128 + wc * 32 + nt * 8 + (lane & 3) * 2;
                float2 e0 = *(const float2*)(emb + (size_t)row * D_IN + col);
                float2 e1 = *(const float2*)(emb + (size_t)(row + 8) * D_IN + col);
                float d0 = accR[mt][nt][0] - e0.x;
                float d1 = accR[mt][nt][1] - e0.y;
                float d2 = accR[mt][nt][2] - e1.x;
                float d3 = accR[mt][nt][3] - e1.y;
                local += d0 * d0 + d1 * d1 + d2 * d2 + d3 * d3;
            }
    }

    // ---- reductions ----
#pragma unroll
    for (int off = 16; off > 0; off >>= 1) {
        rql   += __shfl_xor_sync(0xffffffffu, rql, off);
        local += __shfl_xor_sync(0xffffffffu, local, off);
    }
    if (lane == 0) {
        atomicAdd(&g_rq, (double)rql);
        atomicAdd(&g_recon, (double)local);
    }
}

// ---------------- finalize ----------------
__global__ void k_finalize(float* __restrict__ out, int out_size) {
    __shared__ int cnt[3];
    int t = threadIdx.x;
    if (t < 3) cnt[t] = 0;
    __syncthreads();
    if (t < 3 * NCODE) { if (g_used[t]) atomicAdd(&cnt[t / NCODE], 1); }
    __syncthreads();
    if (t == 0) {
        double recon = g_recon / ((double)NROWS * (double)D_IN);
        double rq    = (1.0 + BETA) * g_rq / ((double)NROWS * (double)DH);
        float rf = (float)recon, qf = (float)rq;
        if (out_size > 0) out[0] = rf + qf;
        if (out_size > 1) out[1] = rf;
        if (out_size > 2) out[2] = qf;
        if (out_size > 3) out[3] = (float)cnt[0];
        if (out_size > 4) out[4] = (float)cnt[1];
        if (out_size > 5) out[5] = (float)cnt[2];
    }
    for (int i = 6 + t; i < out_size; i += blockDim.x) out[i] = 0.f;
}

// ---------------- launch ----------------
extern "C" void kernel_launch(void* const* d_in, const int* in_sizes, int n_in,
                              void* d_out, int out_size) {
    const float* emb  = (const float*)d_in[0];
    const float* Wenc = (const float*)d_in[1];
    const float* Wdec = (const float*)d_in[2];
    const float* cb0  = (const float*)d_in[3];
    const float* cb1  = (const float*)d_in[4];
    const float* cb2  = (const float*)d_in[5];

    cudaFuncSetAttribute(k_fused, cudaFuncAttributeMaxDynamicSharedMemorySize, F_SMEM);

    k_init<<<1, 768>>>();
    k_norms<<<3, 256>>>(cb0, cb1, cb2);
    k_cvt<<<448, 256>>>(Wenc, Wdec, cb0, cb1, cb2);
    k_fused<<<NROWS / 128, 512, F_SMEM>>>(emb, cb0, cb1, cb2);
    k_finalize<<<1, 768>>>((float*)d_out, out_size);
}